// round 7
// baseline (speedup 1.0000x reference)
#include <cuda_runtime.h>
#include <cuda_bf16.h>
#include <math.h>

#define BD 512
#define MD 32768
#define NPREDD 20
#define FUTD 12
#define NROWS (BD*NPREDD)
#define NSLICE 18

// smem: 2 KV buffers then Q staging
// buf b at b*28160: Kh[64][56] bf16 (7168), Kl (7168), Vh[48][72] bf16 (6912), Vl (6912)
#define KVBUF_B   28160
#define OFF_Q     (2*KVBUF_B)
#define SMEM_ATTN (OFF_Q + 64*48*4)

__device__ float g_state[BD*48];
__device__ float g_q[BD*48];
__device__ __nv_bfloat16 g_Kh[MD*48];
__device__ __nv_bfloat16 g_Kl[MD*48];
__device__ __nv_bfloat16 g_Vth[48*MD];
__device__ __nv_bfloat16 g_Vtl[48*MD];
__device__ float g_part[NSLICE*BD*52];
__device__ float g_pred[NROWS*48];
__device__ float g_wTih[96*288];
__device__ float g_wThh[96*288];

__device__ __forceinline__ float sg_(float x){ return 1.f/(1.f+__expf(-x)); }

__device__ __forceinline__ void cpa16(void* dst, const void* src){
    unsigned ds = (unsigned)__cvta_generic_to_shared(dst);
    asm volatile("cp.async.cg.shared.global [%0], [%1], 16;\n" :: "r"(ds), "l"(src));
}

#define MMA_BF16(c, a0,a1,a2,a3, b0,b1) \
    asm volatile("mma.sync.aligned.m16n8k16.row.col.f32.bf16.bf16.f32 " \
        "{%0,%1,%2,%3}, {%4,%5,%6,%7}, {%8,%9}, {%0,%1,%2,%3};" \
        : "+f"(c[0]), "+f"(c[1]), "+f"(c[2]), "+f"(c[3]) \
        : "r"(a0),"r"(a1),"r"(a2),"r"(a3),"r"(b0),"r"(b1))

__device__ __forceinline__ unsigned ldu32(const __nv_bfloat16* p){
    return *(const unsigned*)p;
}
__device__ __forceinline__ unsigned short us_(__nv_bfloat16 h){
    return *(unsigned short*)&h;
}
// pack two floats into bf16x2 (hi) and residual bf16x2 (lo)
__device__ __forceinline__ void split2(float a, float b, unsigned &hi, unsigned &lo){
    __nv_bfloat16 ha = __float2bfloat16(a), hb = __float2bfloat16(b);
    __nv_bfloat16 la = __float2bfloat16(a - __bfloat162float(ha));
    __nv_bfloat16 lb = __float2bfloat16(b - __bfloat162float(hb));
    hi = (unsigned)us_(ha) | ((unsigned)us_(hb) << 16);
    lo = (unsigned)us_(la) | ((unsigned)us_(lb) << 16);
}

// ---------- encoder ----------
__global__ void enc_kernel(const float* __restrict__ past,
    const float* __restrict__ cw, const float* __restrict__ cb,
    const float* __restrict__ wih, const float* __restrict__ whh,
    const float* __restrict__ bih, const float* __restrict__ bhh,
    const float* __restrict__ Wq, const float* __restrict__ bq)
{
    __shared__ float se[8][48];
    __shared__ float sh[48];
    __shared__ float sgi[144], sgh[144];
    int b = blockIdx.x, tid = threadIdx.x;
    for (int idx = tid; idx < 8*48; idx += 144) {
        int t = idx/48, c = idx%48;
        float s = cb[c];
        #pragma unroll
        for (int k = 0; k < 3; k++) {
            int tt = t + k - 1;
            if (tt >= 0 && tt < 8) {
                s = fmaf(cw[c*6+k],   past[b*16+tt*2+0], s);
                s = fmaf(cw[c*6+3+k], past[b*16+tt*2+1], s);
            }
        }
        se[t][c] = fmaxf(s, 0.f);
    }
    if (tid < 48) sh[tid] = 0.f;
    __syncthreads();
    for (int t = 0; t < 8; t++) {
        float gi = bih[tid], gh = bhh[tid];
        const float* wi = wih + tid*48;
        const float* wh = whh + tid*48;
        #pragma unroll 8
        for (int d = 0; d < 48; d++) {
            gi = fmaf(se[t][d], wi[d], gi);
            gh = fmaf(sh[d],    wh[d], gh);
        }
        sgi[tid] = gi; sgh[tid] = gh;
        __syncthreads();
        float hn = 0.f;
        if (tid < 48) {
            float r = sg_(sgi[tid]    + sgh[tid]);
            float z = sg_(sgi[48+tid] + sgh[48+tid]);
            float n = tanhf(sgi[96+tid] + r*sgh[96+tid]);
            hn = (1.f-z)*n + z*sh[tid];
        }
        __syncthreads();
        if (tid < 48) sh[tid] = hn;
        __syncthreads();
    }
    if (tid < 48) {
        g_state[b*48+tid] = sh[tid];
        float q = bq[tid];
        const float* w = Wq + tid*48;
        #pragma unroll 8
        for (int d = 0; d < 48; d++) q = fmaf(sh[d], w[d], q);
        g_q[b*48+tid] = q;
    }
}

// ---------- K projection + hi/lo split (m-major) ----------
__global__ void kproj_kernel(const float* __restrict__ mp,
    const float* __restrict__ Wk, const float* __restrict__ bk)
{
    int idx = blockIdx.x*blockDim.x + threadIdx.x;
    if (idx >= MD*48) return;
    int m = idx/48, j = idx - m*48;
    const float* rp = mp + m*48;
    const float* wk = Wk + j*48;
    float sk = bk[j];
    #pragma unroll 8
    for (int d = 0; d < 48; d++) sk = fmaf(rp[d], wk[d], sk);
    __nv_bfloat16 h = __float2bfloat16(sk);
    g_Kh[idx] = h;
    g_Kl[idx] = __float2bfloat16(sk - __bfloat162float(h));
}

// ---------- V projection + hi/lo split, transposed (d-major) ----------
__global__ void vproj_kernel(const float* __restrict__ mf,
    const float* __restrict__ Wv, const float* __restrict__ bv)
{
    __shared__ float sW[48*48];
    __shared__ float sb[48];
    int tid = threadIdx.x;
    for (int i = tid; i < 48*48; i += 256) sW[i] = Wv[i];
    if (tid < 48) sb[tid] = bv[tid];
    __syncthreads();
    int m = blockIdx.x*256 + tid;
    float r[48];
    #pragma unroll 8
    for (int d = 0; d < 48; d++) r[d] = mf[(size_t)m*48 + d];
    #pragma unroll 1
    for (int j = 0; j < 48; j++) {
        float sv = sb[j];
        const float* w = sW + j*48;
        #pragma unroll 8
        for (int d = 0; d < 48; d++) sv = fmaf(r[d], w[d], sv);
        __nv_bfloat16 h = __float2bfloat16(sv);
        g_Vth[(size_t)j*MD + m] = h;
        g_Vtl[(size_t)j*MD + m] = __float2bfloat16(sv - __bfloat162float(h));
    }
}

// ---------- decoder weight transpose ----------
__global__ void wt_kernel(const float* __restrict__ wih, const float* __restrict__ whh)
{
    int i = blockIdx.x*blockDim.x + threadIdx.x;
    if (i < 288*96) {
        int j = i/96, k = i - j*96;
        g_wTih[k*288+j] = wih[i];
        g_wThh[k*288+j] = whh[i];
    }
}

// ---------- prefetch helper ----------
__device__ __forceinline__ void prefetch_chunk(char* base, int m0, int tid){
    #pragma unroll
    for (int i = tid; i < 768; i += 128) {
        int arr = i / 384;
        int r = (i % 384) / 6, seg = i % 6;
        const char* src = (const char*)(arr ? g_Kl : g_Kh) + ((size_t)(m0+r)*48)*2 + seg*16;
        cpa16(base + arr*7168 + r*112 + seg*16, src);
    }
    #pragma unroll
    for (int i = tid; i < 768; i += 128) {
        int arr = i / 384;
        int r = (i % 384) / 8, seg = i % 8;
        const char* src = (const char*)(arr ? g_Vtl : g_Vth) + ((size_t)r*MD + m0)*2 + seg*16;
        cpa16(base + 14336 + arr*6912 + r*144 + seg*16, src);
    }
}

// ---------- attention: register-resident FA2, bf16-split HMMA ----------
__global__ void __launch_bounds__(128,2) attn_kernel()
{
    extern __shared__ char sm[];
    int tid = threadIdx.x, lane = tid & 31, w = tid >> 5;
    int gid = lane >> 2, tg = lane & 3;
    int qbase = blockIdx.y * 64;
    int s = blockIdx.x;
    int m_start = (s < 8) ? s*1856 : 14848 + (s-8)*1792;
    int nch = (s < 8) ? 29 : 28;

    // stage Q (f32) then build A-fragments hi/lo
    float* sQ = (float*)(sm + OFF_Q);
    for (int i = tid; i < 64*48; i += 128) sQ[i] = g_q[qbase*48 + i];
    __syncthreads();

    unsigned qh[3][4], ql[3][4];
    {
        int r0 = w*16 + gid, r1 = r0 + 8;
        #pragma unroll
        for (int j = 0; j < 3; j++) {
            int c = j*16 + tg*2;
            split2(sQ[r0*48 + c],     sQ[r0*48 + c + 1],     qh[j][0], ql[j][0]);
            split2(sQ[r1*48 + c],     sQ[r1*48 + c + 1],     qh[j][1], ql[j][1]);
            split2(sQ[r0*48 + c + 8], sQ[r0*48 + c + 9],     qh[j][2], ql[j][2]);
            split2(sQ[r1*48 + c + 8], sQ[r1*48 + c + 9],     qh[j][3], ql[j][3]);
        }
    }

    prefetch_chunk(sm, m_start, tid);
    asm volatile("cp.async.commit_group;\n");

    float O[6][4];
    #pragma unroll
    for (int dt = 0; dt < 6; dt++) { O[dt][0]=0.f; O[dt][1]=0.f; O[dt][2]=0.f; O[dt][3]=0.f; }
    float rm0 = -1e30f, rm1 = -1e30f, rs0 = 0.f, rs1 = 0.f;

    for (int c = 0; c < nch; c++) {
        asm volatile("cp.async.wait_group 0;\n" ::: "memory");
        __syncthreads();
        if (c + 1 < nch)
            prefetch_chunk(sm + ((c+1)&1)*KVBUF_B, m_start + (c+1)*64, tid);
        asm volatile("cp.async.commit_group;\n");

        const __nv_bfloat16* Kh = (const __nv_bfloat16*)(sm + (c&1)*KVBUF_B);
        const __nv_bfloat16* Kl = Kh + 64*56;
        const __nv_bfloat16* Vh = (const __nv_bfloat16*)(sm + (c&1)*KVBUF_B + 14336);
        const __nv_bfloat16* Vl = Vh + 48*72;

        // ---- QK^T: warp computes full 16q x 64m ----
        float Sc[8][4];
        #pragma unroll
        for (int nt = 0; nt < 8; nt++) { Sc[nt][0]=0.f; Sc[nt][1]=0.f; Sc[nt][2]=0.f; Sc[nt][3]=0.f; }
        #pragma unroll
        for (int j = 0; j < 3; j++) {
            int kc = j*16 + tg*2;
            #pragma unroll
            for (int nt = 0; nt < 8; nt++) {
                const __nv_bfloat16* kr = Kh + (nt*8+gid)*56 + kc;
                const __nv_bfloat16* lr = Kl + (nt*8+gid)*56 + kc;
                unsigned kh0 = ldu32(kr), kh1 = ldu32(kr + 8);
                unsigned kl0 = ldu32(lr), kl1 = ldu32(lr + 8);
                MMA_BF16(Sc[nt], qh[j][0],qh[j][1],qh[j][2],qh[j][3], kh0,kh1);
                MMA_BF16(Sc[nt], qh[j][0],qh[j][1],qh[j][2],qh[j][3], kl0,kl1);
                MMA_BF16(Sc[nt], ql[j][0],ql[j][1],ql[j][2],ql[j][3], kh0,kh1);
            }
        }

        // ---- in-register online softmax (row = 4 lanes of a quad) ----
        float m0 = Sc[0][0], m1 = Sc[0][2];
        #pragma unroll
        for (int nt = 0; nt < 8; nt++) {
            m0 = fmaxf(m0, fmaxf(Sc[nt][0], Sc[nt][1]));
            m1 = fmaxf(m1, fmaxf(Sc[nt][2], Sc[nt][3]));
        }
        m0 = fmaxf(m0, __shfl_xor_sync(0xffffffffu, m0, 1));
        m0 = fmaxf(m0, __shfl_xor_sync(0xffffffffu, m0, 2));
        m1 = fmaxf(m1, __shfl_xor_sync(0xffffffffu, m1, 1));
        m1 = fmaxf(m1, __shfl_xor_sync(0xffffffffu, m1, 2));
        float nm0 = fmaxf(rm0, m0), nm1 = fmaxf(rm1, m1);
        float f0 = __expf(rm0 - nm0), f1 = __expf(rm1 - nm1);
        rm0 = nm0; rm1 = nm1;
        rs0 *= f0; rs1 *= f1;
        #pragma unroll
        for (int dt = 0; dt < 6; dt++) {
            O[dt][0] *= f0; O[dt][1] *= f0;
            O[dt][2] *= f1; O[dt][3] *= f1;
        }
        // p = exp(S - m), packed hi/lo per tile (c01 = row gid, c23 = row gid+8)
        unsigned p01h[8], p01l[8], p23h[8], p23l[8];
        #pragma unroll
        for (int nt = 0; nt < 8; nt++) {
            float p0 = __expf(Sc[nt][0] - nm0);
            float p1 = __expf(Sc[nt][1] - nm0);
            float p2 = __expf(Sc[nt][2] - nm1);
            float p3 = __expf(Sc[nt][3] - nm1);
            rs0 += p0 + p1; rs1 += p2 + p3;
            split2(p0, p1, p01h[nt], p01l[nt]);
            split2(p2, p3, p23h[nt], p23l[nt]);
        }

        // ---- PV: P[16x64] @ V[64x48] ----
        #pragma unroll
        for (int t = 0; t < 4; t++) {
            unsigned ah0 = p01h[2*t], ah1 = p23h[2*t], ah2 = p01h[2*t+1], ah3 = p23h[2*t+1];
            unsigned al0 = p01l[2*t], al1 = p23l[2*t], al2 = p01l[2*t+1], al3 = p23l[2*t+1];
            int mk = t*16 + tg*2;
            #pragma unroll
            for (int dt = 0; dt < 6; dt++) {
                const __nv_bfloat16* vr = Vh + (dt*8+gid)*72 + mk;
                const __nv_bfloat16* wr = Vl + (dt*8+gid)*72 + mk;
                unsigned vh0 = ldu32(vr), vh1 = ldu32(vr + 8);
                unsigned vl0 = ldu32(wr), vl1 = ldu32(wr + 8);
                MMA_BF16(O[dt], ah0,ah1,ah2,ah3, vh0,vh1);
                MMA_BF16(O[dt], ah0,ah1,ah2,ah3, vl0,vl1);
                MMA_BF16(O[dt], al0,al1,al2,al3, vh0,vh1);
            }
        }
    }

    // ---- epilogue: finish row sums, write partials ----
    rs0 += __shfl_xor_sync(0xffffffffu, rs0, 1);
    rs0 += __shfl_xor_sync(0xffffffffu, rs0, 2);
    rs1 += __shfl_xor_sync(0xffffffffu, rs1, 1);
    rs1 += __shfl_xor_sync(0xffffffffu, rs1, 2);

    int gq0 = qbase + w*16 + gid, gq1 = gq0 + 8;
    float* P0 = g_part + ((size_t)s*BD + gq0)*52;
    float* P1 = g_part + ((size_t)s*BD + gq1)*52;
    #pragma unroll
    for (int dt = 0; dt < 6; dt++) {
        int col = dt*8 + tg*2;
        P0[col]   = O[dt][0];
        P0[col+1] = O[dt][1];
        P1[col]   = O[dt][2];
        P1[col+1] = O[dt][3];
    }
    if (tg == 0) {
        P0[48] = rm0; P0[49] = rs0;
        P1[48] = rm1; P1[49] = rs1;
    }
}

// ---------- combine partials + emit pred + next q (8 q per block) ----------
__global__ void combine_kernel(const float* __restrict__ Wq, const float* __restrict__ bq,
                               int iter)
{
    __shared__ float sc[8][48];
    int t = threadIdx.x;
    int ql = t / 48, d = t - ql*48;
    int q = blockIdx.x*8 + ql;
    float gm = -1e30f;
    #pragma unroll
    for (int s = 0; s < NSLICE; s++)
        gm = fmaxf(gm, g_part[((size_t)s*BD+q)*52 + 48]);
    float tot = 0.f, av = 0.f;
    #pragma unroll
    for (int s = 0; s < NSLICE; s++) {
        const float* P = g_part + ((size_t)s*BD+q)*52;
        float e = __expf(P[48] - gm);
        tot = fmaf(P[49], e, tot);
        av  = fmaf(P[d],  e, av);
    }
    float att = av / tot;
    g_pred[(q*NPREDD + iter)*48 + d] = att;
    sc[ql][d] = g_q[q*48+d] + att;
    __syncthreads();
    float qn = bq[d];
    const float* w = Wq + d*48;
    #pragma unroll 8
    for (int k = 0; k < 48; k++) qn = fmaf(sc[ql][k], w[k], qn);
    g_q[q*48+d] = qn;
}

// ---------- decoder: GRU(96) x 12, block = 16 rows, 288 threads ----------
__global__ void __launch_bounds__(288) dec_kernel(
    const float* __restrict__ obs,
    const float* __restrict__ bih, const float* __restrict__ bhh,
    const float* __restrict__ fcw, const float* __restrict__ fcb,
    float* __restrict__ out)
{
    __shared__ float xh[96*16];
    __shared__ float ghs[288*16];
    int tid = threadIdx.x;
    int nbase = blockIdx.x*16;

    for (int i = tid; i < 96*16; i += 288) {
        int k = i >> 4, r = i & 15;
        int n = nbase + r;
        xh[i] = (k < 48) ? g_state[(n/NPREDD)*48 + k] : g_pred[(size_t)n*48 + (k-48)];
    }
    float pres = 0.f;
    if (tid < 32) {
        int n = nbase + (tid >> 1);
        pres = obs[(n/NPREDD)*16 + 14 + (tid & 1)];
    }
    __syncthreads();

    for (int t = 0; t < FUTD; t++) {
        const float* W  = (t == 0) ? g_wTih : g_wThh;
        const float* b0 = (t == 0) ? bih : bhh;
        const float* b1 = (t == 0) ? bhh : bih;
        float acc[16];
        float bb = b0[tid];
        #pragma unroll
        for (int r = 0; r < 16; r++) acc[r] = bb;
        #pragma unroll 4
        for (int k = 0; k < 96; k++) {
            float wv = W[k*288 + tid];
            float4 a0 = *(const float4*)&xh[k*16 + 0];
            float4 a1 = *(const float4*)&xh[k*16 + 4];
            float4 a2 = *(const float4*)&xh[k*16 + 8];
            float4 a3 = *(const float4*)&xh[k*16 + 12];
            acc[0]=fmaf(a0.x,wv,acc[0]);  acc[1]=fmaf(a0.y,wv,acc[1]);
            acc[2]=fmaf(a0.z,wv,acc[2]);  acc[3]=fmaf(a0.w,wv,acc[3]);
            acc[4]=fmaf(a1.x,wv,acc[4]);  acc[5]=fmaf(a1.y,wv,acc[5]);
            acc[6]=fmaf(a1.z,wv,acc[6]);  acc[7]=fmaf(a1.w,wv,acc[7]);
            acc[8]=fmaf(a2.x,wv,acc[8]);  acc[9]=fmaf(a2.y,wv,acc[9]);
            acc[10]=fmaf(a2.z,wv,acc[10]); acc[11]=fmaf(a2.w,wv,acc[11]);
            acc[12]=fmaf(a3.x,wv,acc[12]); acc[13]=fmaf(a3.y,wv,acc[13]);
            acc[14]=fmaf(a3.z,wv,acc[14]); acc[15]=fmaf(a3.w,wv,acc[15]);
        }
        __syncthreads();
        #pragma unroll
        for (int r4 = 0; r4 < 4; r4++)
            *(float4*)&ghs[tid*16 + r4*4] =
                make_float4(acc[r4*4], acc[r4*4+1], acc[r4*4+2], acc[r4*4+3]);
        __syncthreads();

        for (int i = tid; i < 96*16; i += 288) {
            int d = i >> 4, r = i & 15;
            float gr = ghs[d*16 + r];
            float gz = ghs[(96+d)*16 + r];
            float gn = ghs[(192+d)*16 + r];
            float rg = sg_(gr + b1[d]);
            float z  = sg_(gz + b1[96+d]);
            float nn, h;
            if (t == 0) {
                nn = tanhf(gn + rg*b1[192+d]);
                h = (1.f - z)*nn;
            } else {
                nn = tanhf(b1[192+d] + rg*gn);
                h = (1.f - z)*nn + z*xh[d*16 + r];
            }
            xh[d*16 + r] = h;
        }
        __syncthreads();

        if (tid < 32) {
            int r = tid >> 1, c = tid & 1;
            const float* fw = fcw + c*96;
            float s = fcb[c];
            #pragma unroll 8
            for (int d = 0; d < 96; d++) s = fmaf(xh[d*16 + r], fw[d], s);
            pres += s;
            size_t n = nbase + r;
            out[(n*FUTD + t)*2 + c] = pres;
        }
    }
}

extern "C" void kernel_launch(void* const* d_in, const int* in_sizes, int n_in,
                              void* d_out, int out_size)
{
    const float* past    = (const float*)d_in[0];
    const float* obs     = (const float*)d_in[1];
    const float* conv_w  = (const float*)d_in[2];
    const float* conv_b  = (const float*)d_in[3];
    const float* enc_wih = (const float*)d_in[4];
    const float* enc_whh = (const float*)d_in[5];
    const float* enc_bih = (const float*)d_in[6];
    const float* enc_bhh = (const float*)d_in[7];
    const float* mem_p   = (const float*)d_in[8];
    const float* mem_f   = (const float*)d_in[9];
    const float* Wq      = (const float*)d_in[10];
    const float* bq      = (const float*)d_in[11];
    const float* Wk      = (const float*)d_in[12];
    const float* bk      = (const float*)d_in[13];
    const float* Wv      = (const float*)d_in[14];
    const float* bv      = (const float*)d_in[15];
    const float* dec_wih = (const float*)d_in[16];
    const float* dec_whh = (const float*)d_in[17];
    const float* dec_bih = (const float*)d_in[18];
    const float* dec_bhh = (const float*)d_in[19];
    const float* fc_w    = (const float*)d_in[20];
    const float* fc_b    = (const float*)d_in[21];
    float* out = (float*)d_out;

    cudaFuncSetAttribute(attn_kernel,
        cudaFuncAttributeMaxDynamicSharedMemorySize, SMEM_ATTN);

    enc_kernel<<<BD, 144>>>(past, conv_w, conv_b, enc_wih, enc_whh,
                            enc_bih, enc_bhh, Wq, bq);
    kproj_kernel<<<(MD*48 + 255)/256, 256>>>(mem_p, Wk, bk);
    vproj_kernel<<<MD/256, 256>>>(mem_f, Wv, bv);
    wt_kernel<<<(288*96 + 255)/256, 256>>>(dec_wih, dec_whh);

    for (int it = 0; it < NPREDD; it++) {
        attn_kernel<<<dim3(NSLICE, BD/64), 128, SMEM_ATTN>>>();
        combine_kernel<<<64, 384>>>(Wq, bq, it);
    }

    dec_kernel<<<NROWS/16, 288>>>(obs, dec_bih, dec_bhh, fc_w, fc_b, out);
}

// round 8
// speedup vs baseline: 1.8706x; 1.8706x over previous
#include <cuda_runtime.h>
#include <cuda_bf16.h>
#include <math.h>

#define BD 512
#define MD 32768
#define NPREDD 20
#define FUTD 12
#define NROWS (BD*NPREDD)
#define NSLICE 36

// smem: 2 KV buffers then Q staging
// buf b at b*28160: Kh[64][56] bf16 (7168), Kl (7168), Vh[48][72] bf16 (6912), Vl (6912)
#define KVBUF_B   28160
#define OFF_Q     (2*KVBUF_B)
#define SMEM_ATTN (OFF_Q + 64*48*4)

__device__ float g_state[BD*48];
__device__ float g_q[BD*48];
__device__ __nv_bfloat16 g_Kh[MD*48];
__device__ __nv_bfloat16 g_Kl[MD*48];
__device__ __nv_bfloat16 g_Vth[48*MD];
__device__ __nv_bfloat16 g_Vtl[48*MD];
__device__ float g_part[NSLICE*BD*52];
__device__ float g_pred[NROWS*48];
__device__ float g_wTih[96*288];
__device__ float g_wThh[96*288];

__device__ __forceinline__ float sg_(float x){ return 1.f/(1.f+__expf(-x)); }

__device__ __forceinline__ void cpa16(void* dst, const void* src){
    unsigned ds = (unsigned)__cvta_generic_to_shared(dst);
    asm volatile("cp.async.cg.shared.global [%0], [%1], 16;\n" :: "r"(ds), "l"(src));
}

#define MMA_BF16(c, a0,a1,a2,a3, b0,b1) \
    asm volatile("mma.sync.aligned.m16n8k16.row.col.f32.bf16.bf16.f32 " \
        "{%0,%1,%2,%3}, {%4,%5,%6,%7}, {%8,%9}, {%0,%1,%2,%3};" \
        : "+f"(c[0]), "+f"(c[1]), "+f"(c[2]), "+f"(c[3]) \
        : "r"(a0),"r"(a1),"r"(a2),"r"(a3),"r"(b0),"r"(b1))

__device__ __forceinline__ unsigned ldu32(const __nv_bfloat16* p){
    return *(const unsigned*)p;
}
__device__ __forceinline__ unsigned short us_(__nv_bfloat16 h){
    return *(unsigned short*)&h;
}
__device__ __forceinline__ void split2(float a, float b, unsigned &hi, unsigned &lo){
    __nv_bfloat16 ha = __float2bfloat16(a), hb = __float2bfloat16(b);
    __nv_bfloat16 la = __float2bfloat16(a - __bfloat162float(ha));
    __nv_bfloat16 lb = __float2bfloat16(b - __bfloat162float(hb));
    hi = (unsigned)us_(ha) | ((unsigned)us_(hb) << 16);
    lo = (unsigned)us_(la) | ((unsigned)us_(lb) << 16);
}

// ---------- encoder ----------
__global__ void enc_kernel(const float* __restrict__ past,
    const float* __restrict__ cw, const float* __restrict__ cb,
    const float* __restrict__ wih, const float* __restrict__ whh,
    const float* __restrict__ bih, const float* __restrict__ bhh,
    const float* __restrict__ Wq, const float* __restrict__ bq)
{
    __shared__ float se[8][48];
    __shared__ float sh[48];
    __shared__ float sgi[144], sgh[144];
    int b = blockIdx.x, tid = threadIdx.x;
    for (int idx = tid; idx < 8*48; idx += 144) {
        int t = idx/48, c = idx%48;
        float s = cb[c];
        #pragma unroll
        for (int k = 0; k < 3; k++) {
            int tt = t + k - 1;
            if (tt >= 0 && tt < 8) {
                s = fmaf(cw[c*6+k],   past[b*16+tt*2+0], s);
                s = fmaf(cw[c*6+3+k], past[b*16+tt*2+1], s);
            }
        }
        se[t][c] = fmaxf(s, 0.f);
    }
    if (tid < 48) sh[tid] = 0.f;
    __syncthreads();
    for (int t = 0; t < 8; t++) {
        float gi = bih[tid], gh = bhh[tid];
        const float* wi = wih + tid*48;
        const float* wh = whh + tid*48;
        #pragma unroll 8
        for (int d = 0; d < 48; d++) {
            gi = fmaf(se[t][d], wi[d], gi);
            gh = fmaf(sh[d],    wh[d], gh);
        }
        sgi[tid] = gi; sgh[tid] = gh;
        __syncthreads();
        float hn = 0.f;
        if (tid < 48) {
            float r = sg_(sgi[tid]    + sgh[tid]);
            float z = sg_(sgi[48+tid] + sgh[48+tid]);
            float n = tanhf(sgi[96+tid] + r*sgh[96+tid]);
            hn = (1.f-z)*n + z*sh[tid];
        }
        __syncthreads();
        if (tid < 48) sh[tid] = hn;
        __syncthreads();
    }
    if (tid < 48) {
        g_state[b*48+tid] = sh[tid];
        float q = bq[tid];
        const float* w = Wq + tid*48;
        #pragma unroll 8
        for (int d = 0; d < 48; d++) q = fmaf(sh[d], w[d], q);
        g_q[b*48+tid] = q;
    }
}

// ---------- K projection + hi/lo split (m-major) ----------
__global__ void kproj_kernel(const float* __restrict__ mp,
    const float* __restrict__ Wk, const float* __restrict__ bk)
{
    int idx = blockIdx.x*blockDim.x + threadIdx.x;
    if (idx >= MD*48) return;
    int m = idx/48, j = idx - m*48;
    const float* rp = mp + m*48;
    const float* wk = Wk + j*48;
    float sk = bk[j];
    #pragma unroll 8
    for (int d = 0; d < 48; d++) sk = fmaf(rp[d], wk[d], sk);
    __nv_bfloat16 h = __float2bfloat16(sk);
    g_Kh[idx] = h;
    g_Kl[idx] = __float2bfloat16(sk - __bfloat162float(h));
}

// ---------- V projection + hi/lo split, transposed (d-major) ----------
__global__ void vproj_kernel(const float* __restrict__ mf,
    const float* __restrict__ Wv, const float* __restrict__ bv)
{
    __shared__ float sW[48*48];
    __shared__ float sb[48];
    int tid = threadIdx.x;
    for (int i = tid; i < 48*48; i += 256) sW[i] = Wv[i];
    if (tid < 48) sb[tid] = bv[tid];
    __syncthreads();
    int m = blockIdx.x*256 + tid;
    float r[48];
    #pragma unroll 8
    for (int d = 0; d < 48; d++) r[d] = mf[(size_t)m*48 + d];
    #pragma unroll 1
    for (int j = 0; j < 48; j++) {
        float sv = sb[j];
        const float* w = sW + j*48;
        #pragma unroll 8
        for (int d = 0; d < 48; d++) sv = fmaf(r[d], w[d], sv);
        __nv_bfloat16 h = __float2bfloat16(sv);
        g_Vth[(size_t)j*MD + m] = h;
        g_Vtl[(size_t)j*MD + m] = __float2bfloat16(sv - __bfloat162float(h));
    }
}

// ---------- decoder weight transpose ----------
__global__ void wt_kernel(const float* __restrict__ wih, const float* __restrict__ whh)
{
    int i = blockIdx.x*blockDim.x + threadIdx.x;
    if (i < 288*96) {
        int j = i/96, k = i - j*96;
        g_wTih[k*288+j] = wih[i];
        g_wThh[k*288+j] = whh[i];
    }
}

// ---------- prefetch helper ----------
__device__ __forceinline__ void prefetch_chunk(char* base, int m0, int tid){
    #pragma unroll
    for (int i = tid; i < 768; i += 128) {
        int arr = i / 384;
        int r = (i % 384) / 6, seg = i % 6;
        const char* src = (const char*)(arr ? g_Kl : g_Kh) + ((size_t)(m0+r)*48)*2 + seg*16;
        cpa16(base + arr*7168 + r*112 + seg*16, src);
    }
    #pragma unroll
    for (int i = tid; i < 768; i += 128) {
        int arr = i / 384;
        int r = (i % 384) / 8, seg = i % 8;
        const char* src = (const char*)(arr ? g_Vtl : g_Vth) + ((size_t)r*MD + m0)*2 + seg*16;
        cpa16(base + 14336 + arr*6912 + r*144 + seg*16, src);
    }
}

// ---------- attention: register-resident FA2, bf16-split HMMA ----------
__global__ void __launch_bounds__(128,2) attn_kernel()
{
    extern __shared__ char sm[];
    int tid = threadIdx.x, lane = tid & 31, w = tid >> 5;
    int gid = lane >> 2, tg = lane & 3;
    int qbase = blockIdx.y * 64;
    int s = blockIdx.x;
    int m_start = (s < 8) ? s*960 : 7680 + (s-8)*896;
    int nch = (s < 8) ? 15 : 14;

    // stage Q (f32) then build A-fragments hi/lo
    float* sQ = (float*)(sm + OFF_Q);
    for (int i = tid; i < 64*48; i += 128) sQ[i] = g_q[qbase*48 + i];
    __syncthreads();

    unsigned qh[3][4], ql[3][4];
    {
        int r0 = w*16 + gid, r1 = r0 + 8;
        #pragma unroll
        for (int j = 0; j < 3; j++) {
            int c = j*16 + tg*2;
            split2(sQ[r0*48 + c],     sQ[r0*48 + c + 1],     qh[j][0], ql[j][0]);
            split2(sQ[r1*48 + c],     sQ[r1*48 + c + 1],     qh[j][1], ql[j][1]);
            split2(sQ[r0*48 + c + 8], sQ[r0*48 + c + 9],     qh[j][2], ql[j][2]);
            split2(sQ[r1*48 + c + 8], sQ[r1*48 + c + 9],     qh[j][3], ql[j][3]);
        }
    }

    prefetch_chunk(sm, m_start, tid);
    asm volatile("cp.async.commit_group;\n");

    float O[6][4];
    #pragma unroll
    for (int dt = 0; dt < 6; dt++) { O[dt][0]=0.f; O[dt][1]=0.f; O[dt][2]=0.f; O[dt][3]=0.f; }
    float rm0 = -1e30f, rm1 = -1e30f, rs0 = 0.f, rs1 = 0.f;

    for (int c = 0; c < nch; c++) {
        asm volatile("cp.async.wait_group 0;\n" ::: "memory");
        __syncthreads();
        if (c + 1 < nch)
            prefetch_chunk(sm + ((c+1)&1)*KVBUF_B, m_start + (c+1)*64, tid);
        asm volatile("cp.async.commit_group;\n");

        const __nv_bfloat16* Kh = (const __nv_bfloat16*)(sm + (c&1)*KVBUF_B);
        const __nv_bfloat16* Kl = Kh + 64*56;
        const __nv_bfloat16* Vh = (const __nv_bfloat16*)(sm + (c&1)*KVBUF_B + 14336);
        const __nv_bfloat16* Vl = Vh + 48*72;

        // ---- QK^T: warp computes full 16q x 64m ----
        float Sc[8][4];
        #pragma unroll
        for (int nt = 0; nt < 8; nt++) { Sc[nt][0]=0.f; Sc[nt][1]=0.f; Sc[nt][2]=0.f; Sc[nt][3]=0.f; }
        #pragma unroll
        for (int j = 0; j < 3; j++) {
            int kc = j*16 + tg*2;
            #pragma unroll
            for (int nt = 0; nt < 8; nt++) {
                const __nv_bfloat16* kr = Kh + (nt*8+gid)*56 + kc;
                const __nv_bfloat16* lr = Kl + (nt*8+gid)*56 + kc;
                unsigned kh0 = ldu32(kr), kh1 = ldu32(kr + 8);
                unsigned kl0 = ldu32(lr), kl1 = ldu32(lr + 8);
                MMA_BF16(Sc[nt], qh[j][0],qh[j][1],qh[j][2],qh[j][3], kh0,kh1);
                MMA_BF16(Sc[nt], qh[j][0],qh[j][1],qh[j][2],qh[j][3], kl0,kl1);
                MMA_BF16(Sc[nt], ql[j][0],ql[j][1],ql[j][2],ql[j][3], kh0,kh1);
            }
        }

        // ---- in-register online softmax (row = 4 lanes of a quad) ----
        float m0 = Sc[0][0], m1 = Sc[0][2];
        #pragma unroll
        for (int nt = 0; nt < 8; nt++) {
            m0 = fmaxf(m0, fmaxf(Sc[nt][0], Sc[nt][1]));
            m1 = fmaxf(m1, fmaxf(Sc[nt][2], Sc[nt][3]));
        }
        m0 = fmaxf(m0, __shfl_xor_sync(0xffffffffu, m0, 1));
        m0 = fmaxf(m0, __shfl_xor_sync(0xffffffffu, m0, 2));
        m1 = fmaxf(m1, __shfl_xor_sync(0xffffffffu, m1, 1));
        m1 = fmaxf(m1, __shfl_xor_sync(0xffffffffu, m1, 2));
        float nm0 = fmaxf(rm0, m0), nm1 = fmaxf(rm1, m1);
        float f0 = __expf(rm0 - nm0), f1 = __expf(rm1 - nm1);
        rm0 = nm0; rm1 = nm1;
        rs0 *= f0; rs1 *= f1;
        #pragma unroll
        for (int dt = 0; dt < 6; dt++) {
            O[dt][0] *= f0; O[dt][1] *= f0;
            O[dt][2] *= f1; O[dt][3] *= f1;
        }

        // ---- exp + PV in two halves (shorter p live-range) ----
        #pragma unroll
        for (int half = 0; half < 2; half++) {
            unsigned p01h[4], p01l[4], p23h[4], p23l[4];
            #pragma unroll
            for (int k = 0; k < 4; k++) {
                int nt = half*4 + k;
                float p0 = __expf(Sc[nt][0] - nm0);
                float p1 = __expf(Sc[nt][1] - nm0);
                float p2 = __expf(Sc[nt][2] - nm1);
                float p3 = __expf(Sc[nt][3] - nm1);
                rs0 += p0 + p1; rs1 += p2 + p3;
                split2(p0, p1, p01h[k], p01l[k]);
                split2(p2, p3, p23h[k], p23l[k]);
            }
            #pragma unroll
            for (int tt = 0; tt < 2; tt++) {
                int t = half*2 + tt;
                unsigned ah0 = p01h[2*tt],   ah1 = p23h[2*tt];
                unsigned ah2 = p01h[2*tt+1], ah3 = p23h[2*tt+1];
                unsigned al0 = p01l[2*tt],   al1 = p23l[2*tt];
                unsigned al2 = p01l[2*tt+1], al3 = p23l[2*tt+1];
                int mk = t*16 + tg*2;
                #pragma unroll
                for (int dt = 0; dt < 6; dt++) {
                    const __nv_bfloat16* vr = Vh + (dt*8+gid)*72 + mk;
                    const __nv_bfloat16* wr = Vl + (dt*8+gid)*72 + mk;
                    unsigned vh0 = ldu32(vr), vh1 = ldu32(vr + 8);
                    unsigned vl0 = ldu32(wr), vl1 = ldu32(wr + 8);
                    MMA_BF16(O[dt], ah0,ah1,ah2,ah3, vh0,vh1);
                    MMA_BF16(O[dt], ah0,ah1,ah2,ah3, vl0,vl1);
                    MMA_BF16(O[dt], al0,al1,al2,al3, vh0,vh1);
                }
            }
        }
    }

    // ---- epilogue: finish row sums, write partials ----
    rs0 += __shfl_xor_sync(0xffffffffu, rs0, 1);
    rs0 += __shfl_xor_sync(0xffffffffu, rs0, 2);
    rs1 += __shfl_xor_sync(0xffffffffu, rs1, 1);
    rs1 += __shfl_xor_sync(0xffffffffu, rs1, 2);

    int gq0 = qbase + w*16 + gid, gq1 = gq0 + 8;
    float* P0 = g_part + ((size_t)s*BD + gq0)*52;
    float* P1 = g_part + ((size_t)s*BD + gq1)*52;
    #pragma unroll
    for (int dt = 0; dt < 6; dt++) {
        int col = dt*8 + tg*2;
        P0[col]   = O[dt][0];
        P0[col+1] = O[dt][1];
        P1[col]   = O[dt][2];
        P1[col+1] = O[dt][3];
    }
    if (tg == 0) {
        P0[48] = rm0; P0[49] = rs0;
        P1[48] = rm1; P1[49] = rs1;
    }
}

// ---------- combine partials + emit pred + next q (8 q per block) ----------
__global__ void combine_kernel(const float* __restrict__ Wq, const float* __restrict__ bq,
                               int iter)
{
    __shared__ float sc[8][48];
    int t = threadIdx.x;
    int ql = t / 48, d = t - ql*48;
    int q = blockIdx.x*8 + ql;
    float gm = -1e30f;
    #pragma unroll
    for (int s = 0; s < NSLICE; s++)
        gm = fmaxf(gm, g_part[((size_t)s*BD+q)*52 + 48]);
    float tot = 0.f, av = 0.f;
    #pragma unroll
    for (int s = 0; s < NSLICE; s++) {
        const float* P = g_part + ((size_t)s*BD+q)*52;
        float e = __expf(P[48] - gm);
        tot = fmaf(P[49], e, tot);
        av  = fmaf(P[d],  e, av);
    }
    float att = av / tot;
    g_pred[(q*NPREDD + iter)*48 + d] = att;
    sc[ql][d] = g_q[q*48+d] + att;
    __syncthreads();
    float qn = bq[d];
    const float* w = Wq + d*48;
    #pragma unroll 8
    for (int k = 0; k < 48; k++) qn = fmaf(sc[ql][k], w[k], qn);
    g_q[q*48+d] = qn;
}

// ---------- decoder: GRU(96) x 12, block = 16 rows, 288 threads ----------
__global__ void __launch_bounds__(288) dec_kernel(
    const float* __restrict__ obs,
    const float* __restrict__ bih, const float* __restrict__ bhh,
    const float* __restrict__ fcw, const float* __restrict__ fcb,
    float* __restrict__ out)
{
    __shared__ float xh[96*16];
    __shared__ float ghs[288*16];
    int tid = threadIdx.x;
    int nbase = blockIdx.x*16;

    for (int i = tid; i < 96*16; i += 288) {
        int k = i >> 4, r = i & 15;
        int n = nbase + r;
        xh[i] = (k < 48) ? g_state[(n/NPREDD)*48 + k] : g_pred[(size_t)n*48 + (k-48)];
    }
    float pres = 0.f;
    if (tid < 32) {
        int n = nbase + (tid >> 1);
        pres = obs[(n/NPREDD)*16 + 14 + (tid & 1)];
    }
    __syncthreads();

    for (int t = 0; t < FUTD; t++) {
        const float* W  = (t == 0) ? g_wTih : g_wThh;
        const float* b0 = (t == 0) ? bih : bhh;
        const float* b1 = (t == 0) ? bhh : bih;
        float acc[16];
        float bb = b0[tid];
        #pragma unroll
        for (int r = 0; r < 16; r++) acc[r] = bb;
        #pragma unroll 4
        for (int k = 0; k < 96; k++) {
            float wv = W[k*288 + tid];
            float4 a0 = *(const float4*)&xh[k*16 + 0];
            float4 a1 = *(const float4*)&xh[k*16 + 4];
            float4 a2 = *(const float4*)&xh[k*16 + 8];
            float4 a3 = *(const float4*)&xh[k*16 + 12];
            acc[0]=fmaf(a0.x,wv,acc[0]);  acc[1]=fmaf(a0.y,wv,acc[1]);
            acc[2]=fmaf(a0.z,wv,acc[2]);  acc[3]=fmaf(a0.w,wv,acc[3]);
            acc[4]=fmaf(a1.x,wv,acc[4]);  acc[5]=fmaf(a1.y,wv,acc[5]);
            acc[6]=fmaf(a1.z,wv,acc[6]);  acc[7]=fmaf(a1.w,wv,acc[7]);
            acc[8]=fmaf(a2.x,wv,acc[8]);  acc[9]=fmaf(a2.y,wv,acc[9]);
            acc[10]=fmaf(a2.z,wv,acc[10]); acc[11]=fmaf(a2.w,wv,acc[11]);
            acc[12]=fmaf(a3.x,wv,acc[12]); acc[13]=fmaf(a3.y,wv,acc[13]);
            acc[14]=fmaf(a3.z,wv,acc[14]); acc[15]=fmaf(a3.w,wv,acc[15]);
        }
        __syncthreads();
        #pragma unroll
        for (int r4 = 0; r4 < 4; r4++)
            *(float4*)&ghs[tid*16 + r4*4] =
                make_float4(acc[r4*4], acc[r4*4+1], acc[r4*4+2], acc[r4*4+3]);
        __syncthreads();

        for (int i = tid; i < 96*16; i += 288) {
            int d = i >> 4, r = i & 15;
            float gr = ghs[d*16 + r];
            float gz = ghs[(96+d)*16 + r];
            float gn = ghs[(192+d)*16 + r];
            float rg = sg_(gr + b1[d]);
            float z  = sg_(gz + b1[96+d]);
            float nn, h;
            if (t == 0) {
                nn = tanhf(gn + rg*b1[192+d]);
                h = (1.f - z)*nn;
            } else {
                nn = tanhf(b1[192+d] + rg*gn);
                h = (1.f - z)*nn + z*xh[d*16 + r];
            }
            xh[d*16 + r] = h;
        }
        __syncthreads();

        if (tid < 32) {
            int r = tid >> 1, c = tid & 1;
            const float* fw = fcw + c*96;
            float s = fcb[c];
            #pragma unroll 8
            for (int d = 0; d < 96; d++) s = fmaf(xh[d*16 + r], fw[d], s);
            pres += s;
            size_t n = nbase + r;
            out[(n*FUTD + t)*2 + c] = pres;
        }
    }
}

extern "C" void kernel_launch(void* const* d_in, const int* in_sizes, int n_in,
                              void* d_out, int out_size)
{
    const float* past    = (const float*)d_in[0];
    const float* obs     = (const float*)d_in[1];
    const float* conv_w  = (const float*)d_in[2];
    const float* conv_b  = (const float*)d_in[3];
    const float* enc_wih = (const float*)d_in[4];
    const float* enc_whh = (const float*)d_in[5];
    const float* enc_bih = (const float*)d_in[6];
    const float* enc_bhh = (const float*)d_in[7];
    const float* mem_p   = (const float*)d_in[8];
    const float* mem_f   = (const float*)d_in[9];
    const float* Wq      = (const float*)d_in[10];
    const float* bq      = (const float*)d_in[11];
    const float* Wk      = (const float*)d_in[12];
    const float* bk      = (const float*)d_in[13];
    const float* Wv      = (const float*)d_in[14];
    const float* bv      = (const float*)d_in[15];
    const float* dec_wih = (const float*)d_in[16];
    const float* dec_whh = (const float*)d_in[17];
    const float* dec_bih = (const float*)d_in[18];
    const float* dec_bhh = (const float*)d_in[19];
    const float* fc_w    = (const float*)d_in[20];
    const float* fc_b    = (const float*)d_in[21];
    float* out = (float*)d_out;

    cudaFuncSetAttribute(attn_kernel,
        cudaFuncAttributeMaxDynamicSharedMemorySize, SMEM_ATTN);

    enc_kernel<<<BD, 144>>>(past, conv_w, conv_b, enc_wih, enc_whh,
                            enc_bih, enc_bhh, Wq, bq);
    kproj_kernel<<<(MD*48 + 255)/256, 256>>>(mem_p, Wk, bk);
    vproj_kernel<<<MD/256, 256>>>(mem_f, Wv, bv);
    wt_kernel<<<(288*96 + 255)/256, 256>>>(dec_wih, dec_whh);

    for (int it = 0; it < NPREDD; it++) {
        attn_kernel<<<dim3(NSLICE, BD/64), 128, SMEM_ATTN>>>();
        combine_kernel<<<64, 384>>>(Wq, bq, it);
    }

    dec_kernel<<<NROWS/16, 288>>>(obs, dec_bih, dec_bhh, fc_w, fc_b, out);
}